// round 2
// baseline (speedup 1.0000x reference)
#include <cuda_runtime.h>

// Problem constants
#define BB 512
#define TT 256

// Scratch ping-pong buffers for inter-layer hidden sequences (batch-major [B, T, H]).
// Max layer width is 256 -> 512*256*256 floats = 128 MB each.
__device__ float g_bufA[BB * TT * 256];
__device__ float g_bufB[BB * TT * 256];

// One persistent kernel per layer.
//   grid = 128 CTAs, block = 256 threads, each CTA owns 4 batch rows for the
//   whole T=256 scan (recurrence is batch-local -> no cross-CTA dependency).
//   Thread (j = tid % H, bgrp = tid / H) owns NB = H/64 batch rows' outputs
//   at hidden index j. Weights are read from global (L1-cached: smem footprint
//   is kept tiny so the 228KB L1 carveout holds them). h state + staged x_t
//   live in smem; h reads are warp-uniform broadcasts (conflict-free).
template<int FIN, int H, bool FUSE_DENSE>
__global__ void __launch_bounds__(256, 1)
rnn_layer_kernel(const float* __restrict__ x,     // [B, T, FIN]
                 const float* __restrict__ Wx,    // [FIN, H]
                 const float* __restrict__ Wh,    // [H, H]
                 const float* __restrict__ bias,  // [H]
                 float* __restrict__ hout,        // [B, T, H] (unused if FUSE_DENSE)
                 const float* __restrict__ Wd,    // [T*H] (only if FUSE_DENSE)
                 const float* __restrict__ bd,    // [1]
                 float* __restrict__ out)         // [B] (only if FUSE_DENSE)
{
    constexpr int BT = 4;            // batch rows per CTA
    constexpr int NB = H / 64;       // batch rows per thread (256 threads cover BT*H outputs)

    __shared__ __align__(16) float xs[BT][FIN];
    __shared__ __align__(16) float hs[BT][H];
    __shared__ float red[256];

    const int tid  = threadIdx.x;
    const int j    = tid % H;
    const int bgrp = tid / H;
    const int b0   = blockIdx.x * BT;

    // h_0 = 0
    for (int i = tid; i < BT * H; i += 256) (&hs[0][0])[i] = 0.f;
    __syncthreads();

    const float bj = bias[j];
    float dacc = 0.f;

    for (int t = 0; t < TT; ++t) {
        // Stage x_t for the CTA's 4 batch rows (coalesced).
        for (int i = tid; i < BT * FIN; i += 256) {
            int r = i / FIN, k = i % FIN;
            xs[r][k] = x[((b0 + r) * TT + t) * FIN + k];
        }
        __syncthreads();

        float acc[NB];
        #pragma unroll
        for (int i = 0; i < NB; ++i) acc[i] = bj;

        // Input projection: acc += x_t @ Wx  (Wx row k contiguous in j -> coalesced LDG)
        #pragma unroll 4
        for (int k = 0; k < FIN; k += 4) {
            float w0 = Wx[(k + 0) * H + j];
            float w1 = Wx[(k + 1) * H + j];
            float w2 = Wx[(k + 2) * H + j];
            float w3 = Wx[(k + 3) * H + j];
            #pragma unroll
            for (int i = 0; i < NB; ++i) {
                const int bl = bgrp * NB + i;
                float4 v = *(const float4*)&xs[bl][k];
                acc[i] += v.x * w0 + v.y * w1 + v.z * w2 + v.w * w3;
            }
        }

        // Recurrence: acc += h_{t-1} @ Wh
        #pragma unroll 4
        for (int k = 0; k < H; k += 4) {
            float w0 = Wh[(k + 0) * H + j];
            float w1 = Wh[(k + 1) * H + j];
            float w2 = Wh[(k + 2) * H + j];
            float w3 = Wh[(k + 3) * H + j];
            #pragma unroll
            for (int i = 0; i < NB; ++i) {
                const int bl = bgrp * NB + i;
                float4 v = *(const float4*)&hs[bl][k];
                acc[i] += v.x * w0 + v.y * w1 + v.z * w2 + v.w * w3;
            }
        }

        #pragma unroll
        for (int i = 0; i < NB; ++i) acc[i] = fmaxf(acc[i], 0.f);

        if (FUSE_DENSE) {
            // H==64, NB==1: accumulate the final dense dot on the fly.
            dacc += acc[0] * Wd[t * H + j];
        }

        __syncthreads();   // all reads of hs for step t done before overwrite

        #pragma unroll
        for (int i = 0; i < NB; ++i) {
            const int bl = bgrp * NB + i;
            hs[bl][j] = acc[i];
            if (!FUSE_DENSE)
                hout[((b0 + bl) * TT + t) * H + j] = acc[i];
        }
        __syncthreads();   // hs(t) visible before step t+1 reads it
    }

    if (FUSE_DENSE) {
        // Reduce the 64 per-j partials for each of the 4 batch rows.
        red[tid] = dacc;
        __syncthreads();
        if (j == 0) {
            float s = 0.f;
            #pragma unroll 8
            for (int q = 0; q < 64; ++q) s += red[bgrp * 64 + q];
            out[b0 + bgrp] = s + bd[0];
        }
    }
}

extern "C" void kernel_launch(void* const* d_in, const int* in_sizes, int n_in,
                              void* d_out, int out_size)
{
    (void)in_sizes; (void)n_in; (void)out_size;

    const float* x   = (const float*)d_in[0];
    const float* Wx1 = (const float*)d_in[1];
    const float* Wh1 = (const float*)d_in[2];
    const float* b1  = (const float*)d_in[3];
    const float* Wx2 = (const float*)d_in[4];
    const float* Wh2 = (const float*)d_in[5];
    const float* b2  = (const float*)d_in[6];
    const float* Wx3 = (const float*)d_in[7];
    const float* Wh3 = (const float*)d_in[8];
    const float* b3  = (const float*)d_in[9];
    const float* Wx4 = (const float*)d_in[10];
    const float* Wh4 = (const float*)d_in[11];
    const float* b4  = (const float*)d_in[12];
    const float* Wd  = (const float*)d_in[13];
    const float* bd  = (const float*)d_in[14];
    float* out = (float*)d_out;

    float *bufA = nullptr, *bufB = nullptr;
    cudaGetSymbolAddress((void**)&bufA, g_bufA);
    cudaGetSymbolAddress((void**)&bufB, g_bufB);

    const dim3 grid(BB / 4);   // 128 CTAs
    const dim3 block(256);

    // Layer 1: [B,T,64] -> h1 [B,T,128]
    rnn_layer_kernel<64, 128, false><<<grid, block>>>(
        x, Wx1, Wh1, b1, bufA, nullptr, nullptr, nullptr);
    // Layer 2: h1 -> h2 [B,T,256]
    rnn_layer_kernel<128, 256, false><<<grid, block>>>(
        bufA, Wx2, Wh2, b2, bufB, nullptr, nullptr, nullptr);
    // Layer 3: h2 -> h3 [B,T,128]
    rnn_layer_kernel<256, 128, false><<<grid, block>>>(
        bufB, Wx3, Wh3, b3, bufA, nullptr, nullptr, nullptr);
    // Layer 4 (+ fused final dense): h3 -> out [B,1]
    rnn_layer_kernel<128, 64, true><<<grid, block>>>(
        bufA, Wx4, Wh4, b4, nullptr, Wd, bd, out);
}

// round 4
// speedup vs baseline: 1.1694x; 1.1694x over previous
#include <cuda_runtime.h>

#define BB 512
#define TT 256

// Inter-layer hidden sequences, batch-major [B, T, H]. Max H=256 -> 128 MB each.
__device__ float g_bufA[BB * TT * 256];
__device__ float g_bufB[BB * TT * 256];

// One kernel per layer. grid = 128 CTAs (4 batch rows each), block = 256 threads.
// Thread (j = tid % H, p = tid / H) owns output column j and the p-th 1/P slice
// of the k-sum over the virtual weight matrix [Wx; Wh] (FIN+H rows), for ALL
// 4 batch rows (acc[4] in registers) -> each weight LDG feeds 4 FFMAs.
// Per step: compute partials -> smem -> sync -> P-way combine + relu + state
// update (+ optional fused dense) -> sync. x staging for t+1 is issued at step
// top (LDG.cg into regs) and stored to the alternate smem buffer after compute,
// hiding DRAM latency behind the FFMA phase.
template<int FIN, int H, int P, bool FUSE_DENSE>
__global__ void __launch_bounds__(256, 1)
rnn_layer(const float* __restrict__ x,     // [B, T, FIN]
          const float* __restrict__ Wx,    // [FIN, H]
          const float* __restrict__ Wh,    // [H, H]
          const float* __restrict__ bias,  // [H]
          float* __restrict__ hout,        // [B, T, H] (unused if FUSE_DENSE)
          const float* __restrict__ Wd,    // [T*H, 1] (FUSE_DENSE only)
          const float* __restrict__ bd,    // [1]
          float* __restrict__ out)         // [B] (FUSE_DENSE only)
{
    constexpr int BT = 4;                 // batch rows per CTA
    constexpr int JW = H;                 // CTA covers all H columns
    static_assert(JW * P == 256, "block must be 256 threads");
    constexpr int KS = (FIN + H) / P;     // virtual-k rows per partition
    static_assert(KS % 4 == 0 && FIN % 4 == 0 && H % 4 == 0, "vec4");
    constexpr int CNT  = (BT * JW) / 256; // combine pairs per thread
    constexpr int CNTX = (BT * FIN) / 256;// x-stage elements per thread
    static_assert(!FUSE_DENSE || CNT == 1, "dense fusion assumes CNT==1");

    __shared__ __align__(16) float xs[2][BT][FIN];
    __shared__ __align__(16) float hs[BT][H];
    __shared__ __align__(16) float part[P][BT][JW];
    __shared__ float red[256];

    const int tid = threadIdx.x;
    const int j   = tid % JW;
    const int p   = tid / JW;
    const int b0  = blockIdx.x * BT;

    // This thread's k-slice of the concatenated [Wx; Wh] rows.
    const int k0  = p * KS, k1 = k0 + KS;
    const int kx0 = (k0 < FIN) ? k0 : FIN;
    const int kx1 = (k1 < FIN) ? k1 : FIN;
    const int kh0 = (k0 > FIN) ? (k0 - FIN) : 0;
    const int kh1 = (k1 > FIN) ? (k1 - FIN) : 0;

    // Preload bias for the combine pairs this thread owns (fixed across t).
    float bj[CNT];
    #pragma unroll
    for (int q = 0; q < CNT; ++q) bj[q] = bias[(tid + q * 256) % JW];

    // h_0 = 0
    for (int i = tid; i < BT * H; i += 256) (&hs[0][0])[i] = 0.f;

    // Prime xs[0] with x(t=0).
    #pragma unroll
    for (int q = 0; q < CNTX; ++q) {
        int i = tid + q * 256;
        int r = i / FIN, k = i % FIN;
        xs[0][r][k] = __ldcg(&x[((b0 + r) * TT + 0) * FIN + k]);
    }
    __syncthreads();

    float dacc = 0.f;
    int cb = 0;

    for (int t = 0; t < TT; ++t) {
        const int nb = cb ^ 1;

        // Issue next-step x loads early (latency hidden behind compute).
        float xstage[CNTX];
        if (t + 1 < TT) {
            #pragma unroll
            for (int q = 0; q < CNTX; ++q) {
                int i = tid + q * 256;
                int r = i / FIN, k = i % FIN;
                xstage[q] = __ldcg(&x[((b0 + r) * TT + (t + 1)) * FIN + k]);
            }
        }

        float acc[BT];
        #pragma unroll
        for (int r = 0; r < BT; ++r) acc[r] = 0.f;

        // Input-projection slice: weights coalesced across j, reused over 4 rows.
        #pragma unroll 2
        for (int k = kx0; k < kx1; k += 4) {
            const float* w = Wx + k * H + j;
            float w0 = w[0], w1 = w[H], w2 = w[2 * H], w3 = w[3 * H];
            #pragma unroll
            for (int r = 0; r < BT; ++r) {
                float4 v = *(const float4*)&xs[cb][r][k];
                acc[r] = fmaf(v.x, w0, acc[r]);
                acc[r] = fmaf(v.y, w1, acc[r]);
                acc[r] = fmaf(v.z, w2, acc[r]);
                acc[r] = fmaf(v.w, w3, acc[r]);
            }
        }

        // Recurrence slice.
        #pragma unroll 2
        for (int k = kh0; k < kh1; k += 4) {
            const float* w = Wh + k * H + j;
            float w0 = w[0], w1 = w[H], w2 = w[2 * H], w3 = w[3 * H];
            #pragma unroll
            for (int r = 0; r < BT; ++r) {
                float4 v = *(const float4*)&hs[r][k];
                acc[r] = fmaf(v.x, w0, acc[r]);
                acc[r] = fmaf(v.y, w1, acc[r]);
                acc[r] = fmaf(v.z, w2, acc[r]);
                acc[r] = fmaf(v.w, w3, acc[r]);
            }
        }

        // Park partials; also commit the staged x (STS after compute so the
        // LDG latency overlapped the FFMA phase).
        #pragma unroll
        for (int r = 0; r < BT; ++r) part[p][r][j] = acc[r];
        if (t + 1 < TT) {
            #pragma unroll
            for (int q = 0; q < CNTX; ++q) {
                int i = tid + q * 256;
                int r = i / FIN, k = i % FIN;
                xs[nb][r][k] = xstage[q];
            }
        }
        __syncthreads();   // partials + staged x visible; all hs reads done

        // Combine: P-way sum, bias, relu, state update, output.
        #pragma unroll
        for (int q = 0; q < CNT; ++q) {
            int pair = tid + q * 256;
            int r = pair / JW, jj = pair % JW;
            float s = bj[q];
            #pragma unroll
            for (int pp = 0; pp < P; ++pp) s += part[pp][r][jj];
            s = fmaxf(s, 0.f);
            hs[r][jj] = s;
            if (FUSE_DENSE) {
                dacc = fmaf(s, __ldg(&Wd[t * H + jj]), dacc);
            } else {
                __stcg(&hout[((b0 + r) * TT + t) * H + jj], s);
            }
        }
        __syncthreads();   // hs(t) ready for step t+1

        cb = nb;
    }

    if (FUSE_DENSE) {
        // pair layout: r = tid / JW, jj = tid % JW  (CNT == 1)
        red[tid] = dacc;
        __syncthreads();
        if (tid < BT) {
            float s = bd[0];
            #pragma unroll 8
            for (int q = 0; q < JW; ++q) s += red[tid * JW + q];
            out[b0 + tid] = s;
        }
    }
}

extern "C" void kernel_launch(void* const* d_in, const int* in_sizes, int n_in,
                              void* d_out, int out_size)
{
    (void)in_sizes; (void)n_in; (void)out_size;

    const float* x   = (const float*)d_in[0];
    const float* Wx1 = (const float*)d_in[1];
    const float* Wh1 = (const float*)d_in[2];
    const float* b1  = (const float*)d_in[3];
    const float* Wx2 = (const float*)d_in[4];
    const float* Wh2 = (const float*)d_in[5];
    const float* b2  = (const float*)d_in[6];
    const float* Wx3 = (const float*)d_in[7];
    const float* Wh3 = (const float*)d_in[8];
    const float* b3  = (const float*)d_in[9];
    const float* Wx4 = (const float*)d_in[10];
    const float* Wh4 = (const float*)d_in[11];
    const float* b4  = (const float*)d_in[12];
    const float* Wd  = (const float*)d_in[13];
    const float* bd  = (const float*)d_in[14];
    float* out = (float*)d_out;

    float *bufA = nullptr, *bufB = nullptr;
    cudaGetSymbolAddress((void**)&bufA, g_bufA);
    cudaGetSymbolAddress((void**)&bufB, g_bufB);

    const dim3 grid(BB / 4);   // 128 CTAs
    const dim3 block(256);

    // L1: FIN=64,  H=128, P=2  (threads = 128*2)
    rnn_layer<64, 128, 2, false><<<grid, block>>>(
        x, Wx1, Wh1, b1, bufA, nullptr, nullptr, nullptr);
    // L2: FIN=128, H=256, P=1  (threads = 256*1)
    rnn_layer<128, 256, 1, false><<<grid, block>>>(
        bufA, Wx2, Wh2, b2, bufB, nullptr, nullptr, nullptr);
    // L3: FIN=256, H=128, P=2
    rnn_layer<256, 128, 2, false><<<grid, block>>>(
        bufB, Wx3, Wh3, b3, bufA, nullptr, nullptr, nullptr);
    // L4: FIN=128, H=64,  P=4, fused final dense
    rnn_layer<128, 64, 4, true><<<grid, block>>>(
        bufA, Wx4, Wh4, b4, nullptr, Wd, bd, out);
}

// round 5
// speedup vs baseline: 2.8301x; 2.4201x over previous
#include <cuda_runtime.h>

#define BB 512
#define TT 256

// Inter-layer hidden sequences, batch-major [B, T, H]. Max H=256 -> 128 MB each.
__device__ float g_bufA[BB * TT * 256];
__device__ float g_bufB[BB * TT * 256];

// One kernel per layer. grid = 128 CTAs (BT=4 batch rows each), block = 256.
// Thread (j = tid % H, p = tid / H) owns output column j and the p-th slice of
// the virtual weight rows [Wx; Wh] (FIN+H rows). Its KS = (FIN+H)/P weight
// values are loop-invariant: the first KREG live in REGISTERS (loaded once),
// the remaining KSM rows live in (dynamic) shared memory. Activations are
// k-major: buf[2][FIN+H] of float4 = (r0,r1,r2,r3) at virtual row k, so the
// inner loop is: 1 uniform LDS.128 + 4 FFMA per k, zero global traffic.
// P==1 (layer 2): thread owns the full column -> no partial combine, ONE
// barrier per step. P>1: partials through smem, two barriers per step.
template<int FIN, int H, int P, int KREG, bool FUSE_DENSE>
__global__ void __launch_bounds__(256, 1)
rnn_layer(const float* __restrict__ x,     // [B, T, FIN]
          const float* __restrict__ Wx,    // [FIN, H]
          const float* __restrict__ Wh,    // [H, H]
          const float* __restrict__ bias,  // [H]
          float* __restrict__ hout,        // [B, T, H]
          const float* __restrict__ Wd,    // [T*H, 1] (FUSE_DENSE)
          const float* __restrict__ bd,    // [1]
          float* __restrict__ out)         // [B]     (FUSE_DENSE)
{
    constexpr int BT  = 4;
    constexpr int JW  = H;
    constexpr int KV  = FIN + H;          // virtual k rows
    constexpr int KS  = KV / P;           // rows per partition
    constexpr int KSM = KS - KREG;        // smem-resident rows per partition
    constexpr int CNT  = (BT * JW) / 256; // combine pairs per thread (P>1)
    constexpr int CNTX = (BT * FIN) / 256;
    static_assert(JW * P == 256, "block must be 256 threads");
    static_assert(KREG <= KS && KREG >= 0, "bad KREG");
    static_assert(!FUSE_DENSE || CNT == 1, "dense fusion assumes CNT==1");

    extern __shared__ float ws[];                       // [P][KSM][JW]
    __shared__ __align__(16) float4 buf[2][KV];         // x rows then h rows
    __shared__ float part[(P > 1 ? P : 1)][BT][(P > 1 ? JW : 1)];
    __shared__ float red[256];

    const int tid = threadIdx.x;
    const int j   = tid % JW;
    const int p   = tid / JW;
    const int b0  = blockIdx.x * BT;
    const int k0  = p * KS;

    // ---- one-time: register-resident weights (column j, rows k0..k0+KREG) ----
    float w[KREG > 0 ? KREG : 1];
    #pragma unroll
    for (int q = 0; q < KREG; ++q) {
        int v = k0 + q;
        w[q] = (v < FIN) ? __ldg(&Wx[v * H + j]) : __ldg(&Wh[(v - FIN) * H + j]);
    }
    // ---- one-time: smem-resident weight overflow ----
    if (KSM > 0) {
        for (int idx = tid; idx < P * KSM * JW; idx += 256) {
            int pp = idx / (KSM * JW);
            int rem = idx % (KSM * JW);
            int s = rem / JW, jj = rem % JW;
            int v = pp * KS + KREG + s;
            ws[idx] = (v < FIN) ? Wx[v * H + jj] : Wh[(v - FIN) * H + jj];
        }
    }
    // h_0 = 0
    for (int i = tid; i < H; i += 256) buf[0][FIN + i] = make_float4(0.f, 0.f, 0.f, 0.f);
    // prime x(t=0)
    #pragma unroll
    for (int q = 0; q < CNTX; ++q) {
        int i = tid + q * 256, r = i / FIN, k = i % FIN;
        ((float*)buf[0])[k * 4 + r] = __ldcg(&x[((b0 + r) * TT + 0) * FIN + k]);
    }

    const float bjj = bias[j];     // P==1 path
    float bj[CNT];                 // P>1 combine path
    #pragma unroll
    for (int q = 0; q < CNT; ++q) bj[q] = bias[(tid + q * 256) % JW];

    __syncthreads();

    float dacc = 0.f;
    int cb = 0;

    for (int t = 0; t < TT; ++t) {
        const int nb = cb ^ 1;

        // prefetch x(t+1) into regs (latency hidden behind FFMA phase)
        float xst[CNTX];
        if (t + 1 < TT) {
            #pragma unroll
            for (int q = 0; q < CNTX; ++q) {
                int i = tid + q * 256, r = i / FIN, k = i % FIN;
                xst[q] = __ldcg(&x[((b0 + r) * TT + (t + 1)) * FIN + k]);
            }
        }

        float a0 = 0.f, a1 = 0.f, a2 = 0.f, a3 = 0.f;
        const float4* ub = buf[cb] + k0;

        #pragma unroll
        for (int q = 0; q < KREG; ++q) {        // register weights
            float4 v = ub[q];
            a0 = fmaf(v.x, w[q], a0);
            a1 = fmaf(v.y, w[q], a1);
            a2 = fmaf(v.z, w[q], a2);
            a3 = fmaf(v.w, w[q], a3);
        }
        if (KSM > 0) {                           // smem weights (coalesced LDS)
            const float* wsp = ws + (p * KSM) * JW + j;
            #pragma unroll 8
            for (int s = 0; s < KSM; ++s) {
                float4 v = ub[KREG + s];
                float wv = wsp[s * JW];
                a0 = fmaf(v.x, wv, a0);
                a1 = fmaf(v.y, wv, a1);
                a2 = fmaf(v.z, wv, a2);
                a3 = fmaf(v.w, wv, a3);
            }
        }

        if (P == 1) {
            // full column owned by this thread: relu + direct state update
            float4 hv;
            hv.x = fmaxf(a0 + bjj, 0.f);
            hv.y = fmaxf(a1 + bjj, 0.f);
            hv.z = fmaxf(a2 + bjj, 0.f);
            hv.w = fmaxf(a3 + bjj, 0.f);
            buf[nb][FIN + j] = hv;               // STS.128
            if (t + 1 < TT) {
                #pragma unroll
                for (int q = 0; q < CNTX; ++q) {
                    int i = tid + q * 256, r = i / FIN, k = i % FIN;
                    ((float*)buf[nb])[k * 4 + r] = xst[q];
                }
            }
            __stcg(&hout[((b0 + 0) * TT + t) * H + j], hv.x);
            __stcg(&hout[((b0 + 1) * TT + t) * H + j], hv.y);
            __stcg(&hout[((b0 + 2) * TT + t) * H + j], hv.z);
            __stcg(&hout[((b0 + 3) * TT + t) * H + j], hv.w);
            __syncthreads();                     // ONE barrier per step
        } else {
            part[p][0][j] = a0;
            part[p][1][j] = a1;
            part[p][2][j] = a2;
            part[p][3][j] = a3;
            if (t + 1 < TT) {
                #pragma unroll
                for (int q = 0; q < CNTX; ++q) {
                    int i = tid + q * 256, r = i / FIN, k = i % FIN;
                    ((float*)buf[nb])[k * 4 + r] = xst[q];
                }
            }
            __syncthreads();
            #pragma unroll
            for (int q = 0; q < CNT; ++q) {
                int pair = tid + q * 256;
                int r = pair / JW, jj = pair % JW;
                float s = bj[q];
                #pragma unroll
                for (int pp = 0; pp < P; ++pp) s += part[pp][r][jj];
                s = fmaxf(s, 0.f);
                ((float*)buf[nb])[(FIN + jj) * 4 + r] = s;
                if (FUSE_DENSE) {
                    dacc = fmaf(s, __ldg(&Wd[t * H + jj]), dacc);
                } else {
                    __stcg(&hout[((b0 + r) * TT + t) * H + jj], s);
                }
            }
            __syncthreads();
        }
        cb = nb;
    }

    if (FUSE_DENSE) {
        red[tid] = dacc;                  // tid = r*JW + jj (CNT==1)
        __syncthreads();
        if (tid < BT) {
            float s = bd[0];
            #pragma unroll 8
            for (int q = 0; q < JW; ++q) s += red[tid * JW + q];
            out[b0 + tid] = s;
        }
    }
}

extern "C" void kernel_launch(void* const* d_in, const int* in_sizes, int n_in,
                              void* d_out, int out_size)
{
    (void)in_sizes; (void)n_in; (void)out_size;

    const float* x   = (const float*)d_in[0];
    const float* Wx1 = (const float*)d_in[1];
    const float* Wh1 = (const float*)d_in[2];
    const float* b1  = (const float*)d_in[3];
    const float* Wx2 = (const float*)d_in[4];
    const float* Wh2 = (const float*)d_in[5];
    const float* b2  = (const float*)d_in[6];
    const float* Wx3 = (const float*)d_in[7];
    const float* Wh3 = (const float*)d_in[8];
    const float* b3  = (const float*)d_in[9];
    const float* Wx4 = (const float*)d_in[10];
    const float* Wh4 = (const float*)d_in[11];
    const float* b4  = (const float*)d_in[12];
    const float* Wd  = (const float*)d_in[13];
    const float* bd  = (const float*)d_in[14];
    float* out = (float*)d_out;

    float *bufA = nullptr, *bufB = nullptr;
    cudaGetSymbolAddress((void**)&bufA, g_bufA);
    cudaGetSymbolAddress((void**)&bufB, g_bufB);

    const dim3 grid(BB / 4);   // 128 CTAs
    const dim3 block(256);

    // Dynamic smem for weight overflow:
    //   L2: P=1, KSM=192 -> 192*256*4 = 196608 B (needs opt-in)
    //   L3: P=2, KSM=32  -> 2*32*128*4 = 32768 B
    constexpr int DynL2 = 192 * 256 * 4;
    constexpr int DynL3 = 2 * 32 * 128 * 4;
    static int attr_done = 0;
    if (!attr_done) {
        cudaFuncSetAttribute(rnn_layer<128, 256, 1, 192, false>,
                             cudaFuncAttributeMaxDynamicSharedMemorySize, DynL2);
        cudaFuncSetAttribute(rnn_layer<256, 128, 2, 160, false>,
                             cudaFuncAttributeMaxDynamicSharedMemorySize, DynL3);
        attr_done = 1;
    }

    // L1: FIN=64,  H=128, P=2, KS=96,  all in regs
    rnn_layer<64, 128, 2, 96, false><<<grid, block, 0>>>(
        x, Wx1, Wh1, b1, bufA, nullptr, nullptr, nullptr);
    // L2: FIN=128, H=256, P=1, KS=384, 192 regs + 192 rows smem
    rnn_layer<128, 256, 1, 192, false><<<grid, block, DynL2>>>(
        bufA, Wx2, Wh2, b2, bufB, nullptr, nullptr, nullptr);
    // L3: FIN=256, H=128, P=2, KS=192, 160 regs + 32 rows smem
    rnn_layer<256, 128, 2, 160, false><<<grid, block, DynL3>>>(
        bufB, Wx3, Wh3, b3, bufA, nullptr, nullptr, nullptr);
    // L4: FIN=128, H=64,  P=4, KS=48, all in regs, fused dense
    rnn_layer<128, 64, 4, 48, true><<<grid, block, 0>>>(
        bufA, Wx4, Wh4, b4, nullptr, Wd, bd, out);
}